// round 6
// baseline (speedup 1.0000x reference)
#include <cuda_runtime.h>

#define HH 512
#define WW 1024
#define DD 32
#define HWSZ (HH*WW)

// Packed RGBA (A unused) copies of the two source views. 16 MB static scratch.
__device__ float4 g_img[2][HWSZ];

__global__ void pack_kernel(const float* __restrict__ ref, const float* __restrict__ inp) {
    int i = blockIdx.x * blockDim.x + threadIdx.x;
    if (i >= HWSZ) return;
    g_img[0][i] = make_float4(ref[i], ref[i + HWSZ], ref[i + 2 * HWSZ], 0.f);
    g_img[1][i] = make_float4(inp[i], inp[i + HWSZ], inp[i + 2 * HWSZ], 0.f);
}

// Exact f32 constants as the reference's fp32 trace sees them.
#define ANGC   0.006135923151542565f    // f32(2*pi/1024) == f32(pi/512)
#define SCALEF 162.97466172610083f      // f32(W/(2*pi)) == f32(H/pi)
#define TWOPIF 6.283185307179586f       // f32(2*pi)
#define PIF    3.141592653589793f       // f32(pi)

struct Rot { float r00,r01,r02,r10,r11,r12,r20,r21,r22,tx,ty,tz; };

// Bit-exact replica of the reference's fp32 projection chain. DO NOT TOUCH:
// every op here feeds the gx/gy bits whose pole-amplified rounding noise
// cancels against the reference's own.
__device__ __forceinline__ float2 project(const Rot& c, float rx, float ry, float rz) {
    float px = __fadd_rn(fmaf(c.r02, rz, fmaf(c.r01, ry, __fmul_rn(c.r00, rx))), c.tx);
    float py = __fadd_rn(fmaf(c.r12, rz, fmaf(c.r11, ry, __fmul_rn(c.r10, rx))), c.ty);
    float pz = __fadd_rn(fmaf(c.r22, rz, fmaf(c.r21, ry, __fmul_rn(c.r20, rx))), c.tz);
    // norm^2: sequential reduce of squares, no fma contraction.
    float s = __fadd_rn(__fadd_rn(__fmul_rn(px, px), __fmul_rn(py, py)),
                        __fmul_rn(pz, pz));
    // n_z = pz / sqrt(s): IEEE sqrt.rn + div.rn.
    float nz = __fdiv_rn(pz, __fsqrt_rn(s));
    nz = fminf(fmaxf(nz, -1.0f), 1.0f);
    // JAX acos decomposition: 2*atan2(sqrt(1 - x*x), 1 + x), x==-1 -> pi.
    float ph;
    if (nz != -1.0f) {
        float xx = __fmul_rn(nz, nz);
        float yy = __fsqrt_rn(__fadd_rn(1.0f, -xx));
        ph = 2.0f * atan2f(yy, __fadd_rn(1.0f, nz));
    } else {
        ph = PIF;
    }
    // theta = mod(atan2(py, px), 2pi); for x in (-2pi, 0) XLA's mod = x + 2pi.
    float th = atan2f(py, px);
    if (th < 0.0f) th = __fadd_rn(th, TWOPIF);
    float gx = __fadd_rn(__fmul_rn(th, SCALEF), -0.5f);
    float gy = __fadd_rn(__fmul_rn(ph, SCALEF), -0.5f);
    return make_float2(gx, gy);
}

__device__ __forceinline__ float3 bisample(const float4* __restrict__ im, float gx, float gy) {
    int ix = __float2int_rd(gx);
    int iy = __float2int_rd(gy);
    float wx = gx - (float)ix;
    float wy = gy - (float)iy;
    int x0 = ix & (WW - 1);
    int x1 = (ix + 1) & (WW - 1);          // wrap in x (W power of two)
    int y0 = min(max(iy, 0), HH - 1);      // clamp in y
    int y1 = min(y0 + 1, HH - 1);
    const float4* r0p = im + (y0 << 10);
    const float4* r1p = im + (y1 << 10);
    float4 a = __ldg(r0p + x0);
    float4 b = __ldg(r0p + x1);
    float4 c = __ldg(r1p + x0);
    float4 d = __ldg(r1p + x1);
    float t0x = fmaf(wx, b.x - a.x, a.x);
    float t0y = fmaf(wx, b.y - a.y, a.y);
    float t0z = fmaf(wx, b.z - a.z, a.z);
    float b0x = fmaf(wx, d.x - c.x, c.x);
    float b0y = fmaf(wx, d.y - c.y, c.y);
    float b0z = fmaf(wx, d.z - c.z, c.z);
    float3 o;
    o.x = fmaf(wy, b0x - t0x, t0x);
    o.y = fmaf(wy, b0y - t0y, t0y);
    o.z = fmaf(wy, b0z - t0z, t0z);
    return o;
}

// One block = (pixel-pair tile, view). Each thread owns two adjacent pixels
// (w, w+1): shares phi-sincos / rz / loop+store overhead, doubles ILP, and
// upgrades stores to STG.64.
__global__ void __launch_bounds__(256)
warp_kernel(const float* __restrict__ R0, const float* __restrict__ t0,
            const float* __restrict__ R1, const float* __restrict__ t1,
            const float* __restrict__ radii, float* __restrict__ out) {
    __shared__ float s_r[DD];
    int tid = threadIdx.x;
    if (tid < DD) s_r[tid] = __ldg(radii + tid);
    __syncthreads();

    int v = blockIdx.y;
    int p = blockIdx.x * blockDim.x + tid;     // pixel-pair index
    int idx0 = p << 1;
    int h  = idx0 >> 10;
    int w0 = idx0 & (WW - 1);                  // even; w1 = w0+1 never wraps

    // Pixel-center angles, bit-matching the reference.
    float th0 = __fmul_rn((float)w0 + 0.5f, ANGC);
    float th1 = __fmul_rn((float)(w0 + 1) + 0.5f, ANGC);
    float phi = __fmul_rn((float)h + 0.5f, ANGC);
    float st0 = sinf(th0), ct0 = cosf(th0);
    float st1 = sinf(th1), ct1 = cosf(th1);
    float sp  = sinf(phi), cp  = cosf(phi);
    float dx0 = __fmul_rn(sp, ct0), dy0 = __fmul_rn(sp, st0);
    float dx1 = __fmul_rn(sp, ct1), dy1 = __fmul_rn(sp, st1);
    float dz  = cp;

    const float* R = v ? R1 : R0;
    const float* t = v ? t1 : t0;
    Rot c;
    c.r00 = __ldg(R + 0); c.r01 = __ldg(R + 1); c.r02 = __ldg(R + 2);
    c.r10 = __ldg(R + 3); c.r11 = __ldg(R + 4); c.r12 = __ldg(R + 5);
    c.r20 = __ldg(R + 6); c.r21 = __ldg(R + 7); c.r22 = __ldg(R + 8);
    c.tx  = __ldg(t + 0); c.ty  = __ldg(t + 1); c.tz  = __ldg(t + 2);

    const float4* im = g_img[v];
    float* ob = out + (size_t)(v * 3) * HWSZ + idx0;

#pragma unroll 2
    for (int d = 0; d < DD; d++) {
        float r = s_r[d];
        // pts = radii * dirs (reference scales the direction FIRST)
        float rz  = __fmul_rn(r, dz);
        float rx0 = __fmul_rn(r, dx0), ry0 = __fmul_rn(r, dy0);
        float rx1 = __fmul_rn(r, dx1), ry1 = __fmul_rn(r, dy1);

        float2 g0 = project(c, rx0, ry0, rz);
        float2 g1 = project(c, rx1, ry1, rz);
        float3 s0 = bisample(im, g0.x, g0.y);
        float3 s1 = bisample(im, g1.x, g1.y);

        *(float2*)(ob + 0 * HWSZ) = make_float2(s0.x, s1.x);
        *(float2*)(ob + 1 * HWSZ) = make_float2(s0.y, s1.y);
        *(float2*)(ob + 2 * HWSZ) = make_float2(s0.z, s1.z);
        ob += 6 * HWSZ;
    }
}

extern "C" void kernel_launch(void* const* d_in, const int* in_sizes, int n_in,
                              void* d_out, int out_size) {
    const float* view_ref = (const float*)d_in[0];
    const float* view_inp = (const float*)d_in[1];
    const float* R0 = (const float*)d_in[2];
    const float* t0 = (const float*)d_in[3];
    const float* R1 = (const float*)d_in[4];
    const float* t1 = (const float*)d_in[5];
    const float* radii = (const float*)d_in[6];
    float* out = (float*)d_out;

    pack_kernel<<<(HWSZ + 255) / 256, 256>>>(view_ref, view_inp);
    dim3 grid((HWSZ / 2 + 255) / 256, 2);
    warp_kernel<<<grid, 256>>>(R0, t0, R1, t1, radii, out);
}

// round 7
// speedup vs baseline: 1.2099x; 1.2099x over previous
#include <cuda_runtime.h>

#define HH 512
#define WW 1024
#define DD 32
#define HWSZ (HH*WW)

// Packed RGBA (A unused) copies of the two source views. 16 MB static scratch.
__device__ float4 g_img[2][HWSZ];

__global__ void pack_kernel(const float* __restrict__ ref, const float* __restrict__ inp) {
    int i = blockIdx.x * blockDim.x + threadIdx.x;   // quad index
    if (i >= HWSZ / 4) return;
    const float4* r4 = (const float4*)ref;
    const float4* i4 = (const float4*)inp;
    float4 a0 = r4[i], a1 = r4[i + HWSZ/4], a2 = r4[i + 2*(HWSZ/4)];
    float4 b0 = i4[i], b1 = i4[i + HWSZ/4], b2 = i4[i + 2*(HWSZ/4)];
    int o = i << 2;
    g_img[0][o+0] = make_float4(a0.x, a1.x, a2.x, 0.f);
    g_img[0][o+1] = make_float4(a0.y, a1.y, a2.y, 0.f);
    g_img[0][o+2] = make_float4(a0.z, a1.z, a2.z, 0.f);
    g_img[0][o+3] = make_float4(a0.w, a1.w, a2.w, 0.f);
    g_img[1][o+0] = make_float4(b0.x, b1.x, b2.x, 0.f);
    g_img[1][o+1] = make_float4(b0.y, b1.y, b2.y, 0.f);
    g_img[1][o+2] = make_float4(b0.z, b1.z, b2.z, 0.f);
    g_img[1][o+3] = make_float4(b0.w, b1.w, b2.w, 0.f);
}

// Exact f32 constants as the reference's fp32 trace sees them.
#define ANGC    0.006135923151542565f   // f32(2*pi/1024) == f32(pi/512)
#define SCALEF  162.97466172610083f     // f32(W/(2*pi)) == f32(H/pi)
#define SCALE2F 325.94932345220166f     // 2*SCALEF (folds ph = 2*atan)
#define TWOPIF  6.283185307179586f      // f32(2*pi)
#define PIF     3.141592653589793f
#define PIO2F   1.5707963267948966f

__device__ __forceinline__ float frcp_ap(float x) {
    float r; asm("rcp.approx.f32 %0, %1;" : "=f"(r) : "f"(x)); return r;
}

// atan(t) for t in [0,1], SLEEF single-precision minimax (~1 ulp).
__device__ __forceinline__ float atan_core(float t) {
    float t2 = t * t;
    float u = 0.00282363896258175373f;
    u = fmaf(u, t2, -0.0159569028764963150f);
    u = fmaf(u, t2,  0.0425049886107444763f);
    u = fmaf(u, t2, -0.0748900920152664184f);
    u = fmaf(u, t2,  0.106347933411598205f);
    u = fmaf(u, t2, -0.142027363181114196f);
    u = fmaf(u, t2,  0.199926957488059997f);
    u = fmaf(u, t2, -0.333331018686294555f);
    return fmaf(t2 * u, t, t);
}

// Full-quadrant atan2, ~2.5e-7 rad. (atan2 ulps are UNAMPLIFIED: the pole-
// amplified noise cancellation lives upstream in px/py/nz/yy, which stay
// bit-exact replicas of the reference chain.)
__device__ __forceinline__ float fast_atan2(float y, float x) {
    float ax = fabsf(x), ay = fabsf(y);
    float mx = fmaxf(ax, ay), mn = fminf(ax, ay);
    float a = atan_core(mn * frcp_ap(mx));
    if (ay > ax)  a = PIO2F - a;
    if (x < 0.f)  a = PIF - a;
    return copysignf(a, y);
}

// First-quadrant atan2 (y >= 0, x >= 0) for the acos decomposition.
__device__ __forceinline__ float atan2_pos(float y, float x) {
    float mx = fmaxf(x, y), mn = fminf(x, y);
    float a = atan_core(mn * frcp_ap(mx));
    return (y > x) ? (PIO2F - a) : a;
}

__device__ __forceinline__ float3 bisample(const float4* __restrict__ im, float gx, float gy) {
    int ix = __float2int_rd(gx);
    int iy = __float2int_rd(gy);
    float wx = gx - (float)ix;
    float wy = gy - (float)iy;
    int x0 = ix & (WW - 1);
    int x1 = (ix + 1) & (WW - 1);          // wrap in x (W power of two)
    int y0 = min(max(iy, 0), HH - 1);      // clamp in y
    int y1 = min(y0 + 1, HH - 1);
    const float4* r0p = im + (y0 << 10);
    const float4* r1p = im + (y1 << 10);
    float4 a = __ldg(r0p + x0);
    float4 b = __ldg(r0p + x1);
    float4 c = __ldg(r1p + x0);
    float4 d = __ldg(r1p + x1);
    float t0x = fmaf(wx, b.x - a.x, a.x);
    float t0y = fmaf(wx, b.y - a.y, a.y);
    float t0z = fmaf(wx, b.z - a.z, a.z);
    float b0x = fmaf(wx, d.x - c.x, c.x);
    float b0y = fmaf(wx, d.y - c.y, c.y);
    float b0z = fmaf(wx, d.z - c.z, c.z);
    float3 o;
    o.x = fmaf(wy, b0x - t0x, t0x);
    o.y = fmaf(wy, b0y - t0y, t0y);
    o.z = fmaf(wy, b0z - t0z, t0z);
    return o;
}

// One block = one (pixel-tile, view); blockIdx.y selects the view.
__global__ void __launch_bounds__(256, 6)
warp_kernel(const float* __restrict__ R0, const float* __restrict__ t0,
            const float* __restrict__ R1, const float* __restrict__ t1,
            const float* __restrict__ radii, float* __restrict__ out) {
    __shared__ float s_r[DD];
    int tid = threadIdx.x;
    if (tid < DD) s_r[tid] = __ldg(radii + tid);
    __syncthreads();

    int v = blockIdx.y;
    int idx = blockIdx.x * blockDim.x + tid;
    int h = idx >> 10;
    int w = idx & (WW - 1);

    // Pixel-center angles, bit-matching the reference.
    float theta = __fmul_rn((float)w + 0.5f, ANGC);
    float phi   = __fmul_rn((float)h + 0.5f, ANGC);
    float st = sinf(theta), ct = cosf(theta);
    float sp = sinf(phi),   cp = cosf(phi);
    float dx = __fmul_rn(sp, ct);
    float dy = __fmul_rn(sp, st);
    float dz = cp;

    const float* R = v ? R1 : R0;
    const float* t = v ? t1 : t0;
    float r00 = __ldg(R + 0), r01 = __ldg(R + 1), r02 = __ldg(R + 2);
    float r10 = __ldg(R + 3), r11 = __ldg(R + 4), r12 = __ldg(R + 5);
    float r20 = __ldg(R + 6), r21 = __ldg(R + 7), r22 = __ldg(R + 8);
    float tx = __ldg(t + 0),  ty = __ldg(t + 1),  tz = __ldg(t + 2);

    const float4* im = g_img[v];
    float* ob = out + (size_t)(v * 3) * HWSZ + idx;

#pragma unroll 2
    for (int d = 0; d < DD; d++) {
        float r = s_r[d];
        // ---- bit-exact replica of the reference fp32 chain (DO NOT TOUCH) ----
        float rx = __fmul_rn(r, dx);
        float ry = __fmul_rn(r, dy);
        float rz = __fmul_rn(r, dz);
        float px = __fadd_rn(fmaf(r02, rz, fmaf(r01, ry, __fmul_rn(r00, rx))), tx);
        float py = __fadd_rn(fmaf(r12, rz, fmaf(r11, ry, __fmul_rn(r10, rx))), ty);
        float pz = __fadd_rn(fmaf(r22, rz, fmaf(r21, ry, __fmul_rn(r20, rx))), tz);
        float s = __fadd_rn(__fadd_rn(__fmul_rn(px, px), __fmul_rn(py, py)),
                            __fmul_rn(pz, pz));
        float nz = __fdiv_rn(pz, __fsqrt_rn(s));
        nz = fminf(fmaxf(nz, -1.0f), 1.0f);
        float xx = __fmul_rn(nz, nz);
        float yy = __fsqrt_rn(__fadd_rn(1.0f, -xx));   // pole-amplified: exact
        // ---- end bit-critical section ----

        // acos(nz) = 2*atan2(yy, 1+nz); atan2 ulps unamplified -> fast path.
        float xpn = __fadd_rn(1.0f, nz);
        float ha = atan2_pos(yy, xpn);                 // half-angle
        float gy = (nz != -1.0f) ? fmaf(ha, SCALE2F, -0.5f)
                                 : fmaf(PIF, SCALEF, -0.5f);
        float th = fast_atan2(py, px);
        if (th < 0.0f) th += TWOPIF;
        float gx = fmaf(th, SCALEF, -0.5f);

        float3 smp = bisample(im, gx, gy);
        float* op = ob + (size_t)d * (6 * HWSZ);
        op[0 * HWSZ] = smp.x;
        op[1 * HWSZ] = smp.y;
        op[2 * HWSZ] = smp.z;
    }
}

extern "C" void kernel_launch(void* const* d_in, const int* in_sizes, int n_in,
                              void* d_out, int out_size) {
    const float* view_ref = (const float*)d_in[0];
    const float* view_inp = (const float*)d_in[1];
    const float* R0 = (const float*)d_in[2];
    const float* t0 = (const float*)d_in[3];
    const float* R1 = (const float*)d_in[4];
    const float* t1 = (const float*)d_in[5];
    const float* radii = (const float*)d_in[6];
    float* out = (float*)d_out;

    pack_kernel<<<(HWSZ / 4 + 255) / 256, 256>>>(view_ref, view_inp);
    dim3 grid((HWSZ + 255) / 256, 2);
    warp_kernel<<<grid, 256>>>(R0, t0, R1, t1, radii, out);
}

// round 8
// speedup vs baseline: 1.2354x; 1.0210x over previous
#include <cuda_runtime.h>

#define HH 512
#define WW 1024
#define DD 32
#define HWSZ (HH*WW)

// Packed RGBA (A unused) copies of the two source views. 16 MB static scratch.
__device__ float4 g_img[2][HWSZ];

__global__ void pack_kernel(const float* __restrict__ ref, const float* __restrict__ inp) {
    int i = blockIdx.x * blockDim.x + threadIdx.x;   // quad index
    if (i >= HWSZ / 4) return;
    const float4* r4 = (const float4*)ref;
    const float4* i4 = (const float4*)inp;
    float4 a0 = r4[i], a1 = r4[i + HWSZ/4], a2 = r4[i + 2*(HWSZ/4)];
    float4 b0 = i4[i], b1 = i4[i + HWSZ/4], b2 = i4[i + 2*(HWSZ/4)];
    int o = i << 2;
    g_img[0][o+0] = make_float4(a0.x, a1.x, a2.x, 0.f);
    g_img[0][o+1] = make_float4(a0.y, a1.y, a2.y, 0.f);
    g_img[0][o+2] = make_float4(a0.z, a1.z, a2.z, 0.f);
    g_img[0][o+3] = make_float4(a0.w, a1.w, a2.w, 0.f);
    g_img[1][o+0] = make_float4(b0.x, b1.x, b2.x, 0.f);
    g_img[1][o+1] = make_float4(b0.y, b1.y, b2.y, 0.f);
    g_img[1][o+2] = make_float4(b0.z, b1.z, b2.z, 0.f);
    g_img[1][o+3] = make_float4(b0.w, b1.w, b2.w, 0.f);
}

// Exact f32 constants as the reference's fp32 trace sees them.
#define ANGC    0.006135923151542565f   // f32(2*pi/1024) == f32(pi/512)
#define SCALEF  162.97466172610083f     // f32(W/(2*pi)) == f32(H/pi)
#define SCALE2F 325.94932345220166f     // 2*SCALEF (folds ph = 2*atan)
#define TWOPIF  6.283185307179586f      // f32(2*pi)
#define PIF     3.141592653589793f
#define PIO2F   1.5707963267948966f

__device__ __forceinline__ float frcp_ap(float x) {
    float r; asm("rcp.approx.f32 %0, %1;" : "=f"(r) : "f"(x)); return r;
}

// atan(t) for t in [0,1], SLEEF single-precision minimax (~1 ulp).
__device__ __forceinline__ float atan_core(float t) {
    float t2 = t * t;
    float u = 0.00282363896258175373f;
    u = fmaf(u, t2, -0.0159569028764963150f);
    u = fmaf(u, t2,  0.0425049886107444763f);
    u = fmaf(u, t2, -0.0748900920152664184f);
    u = fmaf(u, t2,  0.106347933411598205f);
    u = fmaf(u, t2, -0.142027363181114196f);
    u = fmaf(u, t2,  0.199926957488059997f);
    u = fmaf(u, t2, -0.333331018686294555f);
    return fmaf(t2 * u, t, t);
}

// atan2 mapped directly into [0, 2pi): quadrant logic folds the reference's
// mod-2pi. y<0 branch computes fl(2pi - a), bit-identical to the old
// copysign-then-add path. (atan2 ulps are UNAMPLIFIED; the pole-noise
// cancellation lives upstream in px/py/nz/yy.)
__device__ __forceinline__ float fast_atan2_2pi(float y, float x) {
    float ax = fabsf(x), ay = fabsf(y);
    float mx = fmaxf(ax, ay), mn = fminf(ax, ay);
    float a = atan_core(mn * frcp_ap(mx));
    if (ay > ax)  a = PIO2F - a;
    if (x < 0.f)  a = PIF - a;
    if (y < 0.f)  a = TWOPIF - a;
    return a;
}

// First-quadrant atan2 (y >= 0, x >= 0) for the acos decomposition.
__device__ __forceinline__ float atan2_pos(float y, float x) {
    float mx = fmaxf(x, y), mn = fminf(x, y);
    float a = atan_core(mn * frcp_ap(mx));
    return (y > x) ? (PIO2F - a) : a;
}

__device__ __forceinline__ float3 bisample(const float4* __restrict__ im, float gx, float gy) {
    int ix = __float2int_rd(gx);
    int iy = __float2int_rd(gy);
    float wx = gx - (float)ix;
    float wy = gy - (float)iy;
    int x0 = ix & (WW - 1);                // handles ix==-1 wrap too
    int x1 = (ix + 1) & (WW - 1);
    int y0 = max(iy, 0);                   // iy <= 511 always (gy < 511.5)
    int y1 = min(y0 + 1, HH - 1);
    const float4* r0p = im + (y0 << 10);
    const float4* r1p = im + (y1 << 10);
    float4 a = __ldg(r0p + x0);
    float4 b = __ldg(r0p + x1);
    float4 c = __ldg(r1p + x0);
    float4 d = __ldg(r1p + x1);
    // weight form: 4 weights + 12 fma (vs 20-op lerp form)
    float u = 1.0f - wx, vv = 1.0f - wy;
    float w00 = u * vv, w01 = wx * vv, w10 = u * wy, w11 = wx * wy;
    float3 o;
    o.x = fmaf(w00, a.x, fmaf(w01, b.x, fmaf(w10, c.x, w11 * d.x)));
    o.y = fmaf(w00, a.y, fmaf(w01, b.y, fmaf(w10, c.y, w11 * d.y)));
    o.z = fmaf(w00, a.z, fmaf(w01, b.z, fmaf(w10, c.z, w11 * d.z)));
    return o;
}

// One block = one (pixel-tile, view); blockIdx.y selects the view.
__global__ void __launch_bounds__(256, 6)
warp_kernel(const float* __restrict__ R0, const float* __restrict__ t0,
            const float* __restrict__ R1, const float* __restrict__ t1,
            const float* __restrict__ radii, float* __restrict__ out) {
    __shared__ float s_r[DD];
    int tid = threadIdx.x;
    if (tid < DD) s_r[tid] = __ldg(radii + tid);
    __syncthreads();

    int v = blockIdx.y;
    int idx = blockIdx.x * blockDim.x + tid;
    int h = idx >> 10;
    int w = idx & (WW - 1);

    // Pixel-center angles, bit-matching the reference.
    float theta = __fmul_rn((float)w + 0.5f, ANGC);
    float phi   = __fmul_rn((float)h + 0.5f, ANGC);
    float st = sinf(theta), ct = cosf(theta);
    float sp = sinf(phi),   cp = cosf(phi);
    float dx = __fmul_rn(sp, ct);
    float dy = __fmul_rn(sp, st);
    float dz = cp;

    const float* R = v ? R1 : R0;
    const float* t = v ? t1 : t0;
    float r00 = __ldg(R + 0), r01 = __ldg(R + 1), r02 = __ldg(R + 2);
    float r10 = __ldg(R + 3), r11 = __ldg(R + 4), r12 = __ldg(R + 5);
    float r20 = __ldg(R + 6), r21 = __ldg(R + 7), r22 = __ldg(R + 8);
    float tx = __ldg(t + 0),  ty = __ldg(t + 1),  tz = __ldg(t + 2);

    const float4* im = g_img[v];
    float* ob = out + (size_t)(v * 3) * HWSZ + idx;

#pragma unroll 2
    for (int d = 0; d < DD; d++) {
        float r = s_r[d];
        // ---- bit-exact replica of the reference fp32 chain (DO NOT TOUCH) ----
        float rx = __fmul_rn(r, dx);
        float ry = __fmul_rn(r, dy);
        float rz = __fmul_rn(r, dz);
        float px = __fadd_rn(fmaf(r02, rz, fmaf(r01, ry, __fmul_rn(r00, rx))), tx);
        float py = __fadd_rn(fmaf(r12, rz, fmaf(r11, ry, __fmul_rn(r10, rx))), ty);
        float pz = __fadd_rn(fmaf(r22, rz, fmaf(r21, ry, __fmul_rn(r20, rx))), tz);
        float s = __fadd_rn(__fadd_rn(__fmul_rn(px, px), __fmul_rn(py, py)),
                            __fmul_rn(pz, pz));
        float nz = __fdiv_rn(pz, __fsqrt_rn(s));
        nz = fminf(fmaxf(nz, -1.0f), 1.0f);
        float xx = __fmul_rn(nz, nz);
        float yy = __fsqrt_rn(__fadd_rn(1.0f, -xx));   // pole-amplified: exact
        // ---- end bit-critical section ----

        // acos(nz) = 2*atan2(yy, 1+nz); guard nz==-1 (atan2_pos(0,0) -> NaN).
        float xpn = __fadd_rn(1.0f, nz);
        float ha = atan2_pos(yy, xpn);                 // half-angle
        float gy = (nz != -1.0f) ? fmaf(ha, SCALE2F, -0.5f)
                                 : fmaf(PIF, SCALEF, -0.5f);
        float th = fast_atan2_2pi(py, px);
        float gx = fmaf(th, SCALEF, -0.5f);

        float3 smp = bisample(im, gx, gy);
        ob[0 * HWSZ] = smp.x;
        ob[1 * HWSZ] = smp.y;
        ob[2 * HWSZ] = smp.z;
        ob += 6 * HWSZ;
    }
}

extern "C" void kernel_launch(void* const* d_in, const int* in_sizes, int n_in,
                              void* d_out, int out_size) {
    const float* view_ref = (const float*)d_in[0];
    const float* view_inp = (const float*)d_in[1];
    const float* R0 = (const float*)d_in[2];
    const float* t0 = (const float*)d_in[3];
    const float* R1 = (const float*)d_in[4];
    const float* t1 = (const float*)d_in[5];
    const float* radii = (const float*)d_in[6];
    float* out = (float*)d_out;

    pack_kernel<<<(HWSZ / 4 + 255) / 256, 256>>>(view_ref, view_inp);
    dim3 grid((HWSZ + 255) / 256, 2);
    warp_kernel<<<grid, 256>>>(R0, t0, R1, t1, radii, out);
}

// round 11
// speedup vs baseline: 1.2371x; 1.0014x over previous
#include <cuda_runtime.h>

#define HH 512
#define WW 1024
#define DD 32
#define HWSZ (HH*WW)

// Packed RGBA (A unused) copies of the two source views. 16 MB static scratch.
__device__ float4 g_img[2][HWSZ];

__global__ void pack_kernel(const float* __restrict__ ref, const float* __restrict__ inp) {
    int i = blockIdx.x * blockDim.x + threadIdx.x;   // quad index
    if (i >= HWSZ / 4) return;
    const float4* r4 = (const float4*)ref;
    const float4* i4 = (const float4*)inp;
    float4 a0 = r4[i], a1 = r4[i + HWSZ/4], a2 = r4[i + 2*(HWSZ/4)];
    float4 b0 = i4[i], b1 = i4[i + HWSZ/4], b2 = i4[i + 2*(HWSZ/4)];
    int o = i << 2;
    g_img[0][o+0] = make_float4(a0.x, a1.x, a2.x, 0.f);
    g_img[0][o+1] = make_float4(a0.y, a1.y, a2.y, 0.f);
    g_img[0][o+2] = make_float4(a0.z, a1.z, a2.z, 0.f);
    g_img[0][o+3] = make_float4(a0.w, a1.w, a2.w, 0.f);
    g_img[1][o+0] = make_float4(b0.x, b1.x, b2.x, 0.f);
    g_img[1][o+1] = make_float4(b0.y, b1.y, b2.y, 0.f);
    g_img[1][o+2] = make_float4(b0.z, b1.z, b2.z, 0.f);
    g_img[1][o+3] = make_float4(b0.w, b1.w, b2.w, 0.f);
}

// Exact f32 constants as the reference's fp32 trace sees them.
#define ANGC    0.006135923151542565f   // f32(2*pi/1024) == f32(pi/512)
#define SCALEF  162.97466172610083f     // f32(W/(2*pi)) == f32(H/pi) = 512/pi
#define SCALE2F 325.94932345220166f     // 2*SCALEF
#define PIF     3.141592653589793f
#define MAGICF  12582912.0f             // 2^23 + 2^22: float->int round trick

__device__ __forceinline__ float frcp_ap(float x) {
    float r; asm("rcp.approx.f32 %0, %1;" : "=f"(r) : "f"(x)); return r;
}
__device__ __forceinline__ float fsqrt_ap(float x) {
    float r; asm("sqrt.approx.f32 %0, %1;" : "=f"(r) : "f"(x)); return r;
}

// S * atan(t) for t in [0,1]: SLEEF 8-coef minimax (~1 ulp) with the grid
// scale folded into the final step.
__device__ __forceinline__ float atan_core_s(float t, float S) {
    float t2 = t * t;
    float u = 0.00282363896258175373f;
    u = fmaf(u, t2, -0.0159569028764963150f);
    u = fmaf(u, t2,  0.0425049886107444763f);
    u = fmaf(u, t2, -0.0748900920152664184f);
    u = fmaf(u, t2,  0.106347933411598205f);
    u = fmaf(u, t2, -0.142027363181114196f);
    u = fmaf(u, t2,  0.199926957488059997f);
    u = fmaf(u, t2, -0.333331018686294555f);
    float st = S * t;
    return fmaf(t2 * u, st, st);
}

// SCALEF * mod(atan2(y,x), 2pi): quadrant constants are exact (SCALEF*pi/2
// = 256, *pi = 512, *2pi = 1024). atan2 ulps are UNAMPLIFIED; the pole-noise
// cancellation lives upstream in px/py/nz (which stay bit-exact).
__device__ __forceinline__ float atan2_2pi_s(float y, float x) {
    float ax = fabsf(x), ay = fabsf(y);
    float mx = fmaxf(ax, ay), mn = fminf(ax, ay);
    float a = atan_core_s(mn * frcp_ap(mx), SCALEF);
    if (ay > ax)  a = 256.0f - a;
    if (x < 0.f)  a = 512.0f - a;
    if (y < 0.f)  a = 1024.0f - a;
    return a;
}

// SCALE2F * atan2(y,x) for y,x >= 0 (acos half-angle path). SCALE2F*pi/2 = 512.
__device__ __forceinline__ float atan2_pos_s(float y, float x) {
    float mx = fmaxf(x, y), mn = fminf(x, y);
    float a = atan_core_s(mn * frcp_ap(mx), SCALE2F);
    return (y > x) ? (512.0f - a) : a;
}

__device__ __forceinline__ float3 bisample(const float4* __restrict__ im, float gx, float gy) {
    // Magic-number floor: f = (g-0.5)+MAGIC rounds to floor(g)+MAGIC (ulp=1 in
    // [2^23,2^24)); mantissa low 23 bits = 0x400000 + floor(g), exact.
    float fx = (gx - 0.5f) + MAGICF;
    float fy = (gy - 0.5f) + MAGICF;
    float wx = gx - (fx - MAGICF);
    float wy = gy - (fy - MAGICF);
    int bx = __float_as_int(fx);
    int x0 = bx & (WW - 1);                // 0x400000 is a multiple of 1024
    int x1 = (bx + 1) & (WW - 1);
    int iy = (__float_as_int(fy) & 0x7FFFFF) - 0x400000;   // in [-1, 511]
    int y0 = max(iy, 0);
    int y1 = min(y0 + 1, HH - 1);
    const float4* r0p = im + (y0 << 10);
    const float4* r1p = im + (y1 << 10);
    float4 a = __ldg(r0p + x0);
    float4 b = __ldg(r0p + x1);
    float4 c = __ldg(r1p + x0);
    float4 d = __ldg(r1p + x1);
    float u = 1.0f - wx, vv = 1.0f - wy;
    float w00 = u * vv, w01 = wx * vv, w10 = u * wy, w11 = wx * wy;
    float3 o;
    o.x = fmaf(w00, a.x, fmaf(w01, b.x, fmaf(w10, c.x, w11 * d.x)));
    o.y = fmaf(w00, a.y, fmaf(w01, b.y, fmaf(w10, c.y, w11 * d.y)));
    o.z = fmaf(w00, a.z, fmaf(w01, b.z, fmaf(w10, c.z, w11 * d.z)));
    return o;
}

// One block = one (pixel-tile, view); blockIdx.y selects the view.
__global__ void __launch_bounds__(256, 6)
warp_kernel(const float* __restrict__ R0, const float* __restrict__ t0,
            const float* __restrict__ R1, const float* __restrict__ t1,
            const float* __restrict__ radii, float* __restrict__ out) {
    __shared__ float s_r[DD];
    int tid = threadIdx.x;
    if (tid < DD) s_r[tid] = __ldg(radii + tid);
    __syncthreads();

    int v = blockIdx.y;
    int idx = blockIdx.x * blockDim.x + tid;
    int h = idx >> 10;
    int w = idx & (WW - 1);

    // Pixel-center angles, bit-matching the reference.
    float theta = __fmul_rn((float)w + 0.5f, ANGC);
    float phi   = __fmul_rn((float)h + 0.5f, ANGC);
    float st = sinf(theta), ct = cosf(theta);
    float sp = sinf(phi),   cp = cosf(phi);
    float dx = __fmul_rn(sp, ct);
    float dy = __fmul_rn(sp, st);
    float dz = cp;

    const float* R = v ? R1 : R0;
    const float* t = v ? t1 : t0;
    float r00 = __ldg(R + 0), r01 = __ldg(R + 1), r02 = __ldg(R + 2);
    float r10 = __ldg(R + 3), r11 = __ldg(R + 4), r12 = __ldg(R + 5);
    float r20 = __ldg(R + 6), r21 = __ldg(R + 7), r22 = __ldg(R + 8);
    float tx = __ldg(t + 0),  ty = __ldg(t + 1),  tz = __ldg(t + 2);

    const float4* im = g_img[v];
    float* ob = out + (size_t)(v * 3) * HWSZ + idx;

#pragma unroll 2
    for (int d = 0; d < DD; d++) {
        float r = s_r[d];
        // ---- bit-exact replica of the reference fp32 chain (DO NOT TOUCH).
        // R10 proved nz is THE load-bearing op: a 2-3 ulp rsqrt deviation in
        // nz re-injects the ref's pole-amplified acos noise at 3-6x amplitude
        // (rel_err 0.977e-3 -> 1.269e-3). div.rn + sqrt.rn, forever. ----
        float rx = __fmul_rn(r, dx);
        float ry = __fmul_rn(r, dy);
        float rz = __fmul_rn(r, dz);
        float px = __fadd_rn(fmaf(r02, rz, fmaf(r01, ry, __fmul_rn(r00, rx))), tx);
        float py = __fadd_rn(fmaf(r12, rz, fmaf(r11, ry, __fmul_rn(r10, rx))), ty);
        float pz = __fadd_rn(fmaf(r22, rz, fmaf(r21, ry, __fmul_rn(r20, rx))), tz);
        float s = __fadd_rn(__fadd_rn(__fmul_rn(px, px), __fmul_rn(py, py)),
                            __fmul_rn(pz, pz));
        float nz = __fdiv_rn(pz, __fsqrt_rn(s));
        nz = fminf(fmaxf(nz, -1.0f), 1.0f);
        // ---- end bit-critical section ----

        // yy: sqrt.approx is safe GIVEN bit-exact nz — its relative ulps move
        // atan2(yy, 1+nz) by <= delta/2 rad-relative at both poles.
        float xx = __fmul_rn(nz, nz);
        float yy = fsqrt_ap(__fadd_rn(1.0f, -xx));

        // acos(nz) = 2*atan2(yy, 1+nz); guard nz==-1 (atan of 0/0 -> NaN).
        float xpn = __fadd_rn(1.0f, nz);
        float ha_s = atan2_pos_s(yy, xpn);             // SCALE2F*half-angle
        float gy = (nz != -1.0f) ? (ha_s - 0.5f)
                                 : fmaf(PIF, SCALEF, -0.5f);
        float gx = atan2_2pi_s(py, px) - 0.5f;

        float3 smp = bisample(im, gx, gy);
        ob[0 * HWSZ] = smp.x;
        ob[1 * HWSZ] = smp.y;
        ob[2 * HWSZ] = smp.z;
        ob += 6 * HWSZ;
    }
}

extern "C" void kernel_launch(void* const* d_in, const int* in_sizes, int n_in,
                              void* d_out, int out_size) {
    const float* view_ref = (const float*)d_in[0];
    const float* view_inp = (const float*)d_in[1];
    const float* R0 = (const float*)d_in[2];
    const float* t0 = (const float*)d_in[3];
    const float* R1 = (const float*)d_in[4];
    const float* t1 = (const float*)d_in[5];
    const float* radii = (const float*)d_in[6];
    float* out = (float*)d_out;

    pack_kernel<<<(HWSZ / 4 + 255) / 256, 256>>>(view_ref, view_inp);
    dim3 grid((HWSZ + 255) / 256, 2);
    warp_kernel<<<grid, 256>>>(R0, t0, R1, t1, radii, out);
}

// round 12
// speedup vs baseline: 1.2638x; 1.0215x over previous
#include <cuda_runtime.h>

#define HH 512
#define WW 1024
#define DD 32
#define HWSZ (HH*WW)

// Packed RGBA (A unused) copies of the two source views. 16 MB static scratch.
__device__ float4 g_img[2][HWSZ];

__global__ void pack_kernel(const float* __restrict__ ref, const float* __restrict__ inp) {
    int i = blockIdx.x * blockDim.x + threadIdx.x;   // quad index
    if (i >= HWSZ / 4) return;
    const float4* r4 = (const float4*)ref;
    const float4* i4 = (const float4*)inp;
    float4 a0 = r4[i], a1 = r4[i + HWSZ/4], a2 = r4[i + 2*(HWSZ/4)];
    float4 b0 = i4[i], b1 = i4[i + HWSZ/4], b2 = i4[i + 2*(HWSZ/4)];
    int o = i << 2;
    g_img[0][o+0] = make_float4(a0.x, a1.x, a2.x, 0.f);
    g_img[0][o+1] = make_float4(a0.y, a1.y, a2.y, 0.f);
    g_img[0][o+2] = make_float4(a0.z, a1.z, a2.z, 0.f);
    g_img[0][o+3] = make_float4(a0.w, a1.w, a2.w, 0.f);
    g_img[1][o+0] = make_float4(b0.x, b1.x, b2.x, 0.f);
    g_img[1][o+1] = make_float4(b0.y, b1.y, b2.y, 0.f);
    g_img[1][o+2] = make_float4(b0.z, b1.z, b2.z, 0.f);
    g_img[1][o+3] = make_float4(b0.w, b1.w, b2.w, 0.f);
}

// Exact f32 constants as the reference's fp32 trace sees them.
#define ANGC    0.006135923151542565f   // f32(2*pi/1024) == f32(pi/512)
#define SCALEF  162.97466172610083f     // f32(W/(2*pi)) == f32(H/pi) = 512/pi
#define SCALE2F 325.94932345220166f     // 2*SCALEF
#define PIF     3.141592653589793f
#define MAGICF  12582912.0f             // 2^23 + 2^22: float->int round trick

__device__ __forceinline__ float frcp_ap(float x) {
    float r; asm("rcp.approx.f32 %0, %1;" : "=f"(r) : "f"(x)); return r;
}
__device__ __forceinline__ float frsqrt_ap(float x) {
    float r; asm("rsqrt.approx.f32 %0, %1;" : "=f"(r) : "f"(x)); return r;
}
__device__ __forceinline__ float fsqrt_ap(float x) {
    float r; asm("sqrt.approx.f32 %0, %1;" : "=f"(r) : "f"(x)); return r;
}

// S * atan(t) for t in [0,1]: SLEEF 8-coef minimax (~1 ulp) with the grid
// scale folded into the final step.
__device__ __forceinline__ float atan_core_s(float t, float S) {
    float t2 = t * t;
    float u = 0.00282363896258175373f;
    u = fmaf(u, t2, -0.0159569028764963150f);
    u = fmaf(u, t2,  0.0425049886107444763f);
    u = fmaf(u, t2, -0.0748900920152664184f);
    u = fmaf(u, t2,  0.106347933411598205f);
    u = fmaf(u, t2, -0.142027363181114196f);
    u = fmaf(u, t2,  0.199926957488059997f);
    u = fmaf(u, t2, -0.333331018686294555f);
    float st = S * t;
    return fmaf(t2 * u, st, st);
}

// SCALEF * mod(atan2(y,x), 2pi): quadrant constants are exact (SCALEF*pi/2
// = 256, *pi = 512, *2pi = 1024). atan2 ulps are UNAMPLIFIED; the pole-noise
// cancellation lives upstream in px/py/nz (which stay bit-exact).
__device__ __forceinline__ float atan2_2pi_s(float y, float x) {
    float ax = fabsf(x), ay = fabsf(y);
    float mx = fmaxf(ax, ay), mn = fminf(ax, ay);
    float a = atan_core_s(mn * frcp_ap(mx), SCALEF);
    if (ay > ax)  a = 256.0f - a;
    if (x < 0.f)  a = 512.0f - a;
    if (y < 0.f)  a = 1024.0f - a;
    return a;
}

// SCALE2F * atan2(y,x) for y,x >= 0 (acos half-angle path). SCALE2F*pi/2 = 512.
__device__ __forceinline__ float atan2_pos_s(float y, float x) {
    float mx = fmaxf(x, y), mn = fminf(x, y);
    float a = atan_core_s(mn * frcp_ap(mx), SCALE2F);
    return (y > x) ? (512.0f - a) : a;
}

__device__ __forceinline__ float3 bisample(const float4* __restrict__ im, float gx, float gy) {
    // Magic-number floor: f = (g-0.5)+MAGIC rounds to floor(g)+MAGIC (ulp=1 in
    // [2^23,2^24)); mantissa low 23 bits = 0x400000 + floor(g), exact.
    float fx = (gx - 0.5f) + MAGICF;
    float fy = (gy - 0.5f) + MAGICF;
    float wx = gx - (fx - MAGICF);
    float wy = gy - (fy - MAGICF);
    int bx = __float_as_int(fx);
    int x0 = bx & (WW - 1);                // 0x400000 is a multiple of 1024
    int x1 = (bx + 1) & (WW - 1);
    int iy = (__float_as_int(fy) & 0x7FFFFF) - 0x400000;   // in [-1, 511]
    int y0 = max(iy, 0);
    int y1 = min(y0 + 1, HH - 1);
    const float4* r0p = im + (y0 << 10);
    const float4* r1p = im + (y1 << 10);
    float4 a = __ldg(r0p + x0);
    float4 b = __ldg(r0p + x1);
    float4 c = __ldg(r1p + x0);
    float4 d = __ldg(r1p + x1);
    float u = 1.0f - wx, vv = 1.0f - wy;
    float w00 = u * vv, w01 = wx * vv, w10 = u * wy, w11 = wx * wy;
    float3 o;
    o.x = fmaf(w00, a.x, fmaf(w01, b.x, fmaf(w10, c.x, w11 * d.x)));
    o.y = fmaf(w00, a.y, fmaf(w01, b.y, fmaf(w10, c.y, w11 * d.y)));
    o.z = fmaf(w00, a.z, fmaf(w01, b.z, fmaf(w10, c.z, w11 * d.z)));
    return o;
}

// One block = one (pixel-tile, view); blockIdx.y selects the view.
__global__ void __launch_bounds__(256, 6)
warp_kernel(const float* __restrict__ R0, const float* __restrict__ t0,
            const float* __restrict__ R1, const float* __restrict__ t1,
            const float* __restrict__ radii, float* __restrict__ out) {
    __shared__ float s_r[DD];
    int tid = threadIdx.x;
    if (tid < DD) s_r[tid] = __ldg(radii + tid);
    __syncthreads();

    int v = blockIdx.y;
    int idx = blockIdx.x * blockDim.x + tid;
    int h = idx >> 10;
    int w = idx & (WW - 1);

    // Pixel-center angles, bit-matching the reference.
    float theta = __fmul_rn((float)w + 0.5f, ANGC);
    float phi   = __fmul_rn((float)h + 0.5f, ANGC);
    float st = sinf(theta), ct = cosf(theta);
    float sp = sinf(phi),   cp = cosf(phi);
    float dx = __fmul_rn(sp, ct);
    float dy = __fmul_rn(sp, st);
    float dz = cp;

    const float* R = v ? R1 : R0;
    const float* t = v ? t1 : t0;
    float r00 = __ldg(R + 0), r01 = __ldg(R + 1), r02 = __ldg(R + 2);
    float r10 = __ldg(R + 3), r11 = __ldg(R + 4), r12 = __ldg(R + 5);
    float r20 = __ldg(R + 6), r21 = __ldg(R + 7), r22 = __ldg(R + 8);
    float tx = __ldg(t + 0),  ty = __ldg(t + 1),  tz = __ldg(t + 2);

    const float4* im = g_img[v];
    float* ob = out + (size_t)(v * 3) * HWSZ + idx;

#pragma unroll 2
    for (int d = 0; d < DD; d++) {
        float r = s_r[d];
        // ---- replica of the reference fp32 chain ----
        float rx = __fmul_rn(r, dx);
        float ry = __fmul_rn(r, dy);
        float rz = __fmul_rn(r, dz);
        float px = __fadd_rn(fmaf(r02, rz, fmaf(r01, ry, __fmul_rn(r00, rx))), tx);
        float py = __fadd_rn(fmaf(r12, rz, fmaf(r11, ry, __fmul_rn(r10, rx))), ty);
        float pz = __fadd_rn(fmaf(r22, rz, fmaf(r21, ry, __fmul_rn(r20, rx))), tz);
        float sxy = __fadd_rn(__fmul_rn(px, px), __fmul_rn(py, py));
        float s   = __fadd_rn(sxy, __fmul_rn(pz, pz));

        // Gated normalize. Amplification of a Δnz into the polar grid coord
        // is SCALEF*Δnz/sin(phi_sampled); sin^2(phi_s) = sxy/s. Where
        // sin(phi_s) >= 0.25 (97% of samples), rsqrt.approx+Newton (~2 ulp)
        // costs <= 9e-5 px — invisible. Near-pole samples (3%, warp-coherent
        // rows) take the bit-exact div.rn/sqrt.rn path that R10 proved is
        // load-bearing there.
        float ir = frsqrt_ap(s);
        float e  = (0.5f * s) * ir;
        ir = ir * fmaf(-e, ir, 1.5f);
        float nz = pz * ir;
        if (sxy < 0.0625f * s) {
            nz = __fdiv_rn(pz, __fsqrt_rn(s));   // rare, branch-skipped
        }
        nz = fminf(fmaxf(nz, -1.0f), 1.0f);

        // yy: sqrt.approx safe (relative ulps only, unamplified downstream).
        float xx = __fmul_rn(nz, nz);
        float yy = fsqrt_ap(__fadd_rn(1.0f, -xx));

        // acos(nz) = 2*atan2(yy, 1+nz); guard nz==-1 (atan of 0/0 -> NaN).
        float xpn = __fadd_rn(1.0f, nz);
        float ha_s = atan2_pos_s(yy, xpn);             // SCALE2F*half-angle
        float gy = (nz != -1.0f) ? (ha_s - 0.5f)
                                 : fmaf(PIF, SCALEF, -0.5f);
        float gx = atan2_2pi_s(py, px) - 0.5f;

        float3 smp = bisample(im, gx, gy);
        ob[0 * HWSZ] = smp.x;
        ob[1 * HWSZ] = smp.y;
        ob[2 * HWSZ] = smp.z;
        ob += 6 * HWSZ;
    }
}

extern "C" void kernel_launch(void* const* d_in, const int* in_sizes, int n_in,
                              void* d_out, int out_size) {
    const float* view_ref = (const float*)d_in[0];
    const float* view_inp = (const float*)d_in[1];
    const float* R0 = (const float*)d_in[2];
    const float* t0 = (const float*)d_in[3];
    const float* R1 = (const float*)d_in[4];
    const float* t1 = (const float*)d_in[5];
    const float* radii = (const float*)d_in[6];
    float* out = (float*)d_out;

    pack_kernel<<<(HWSZ / 4 + 255) / 256, 256>>>(view_ref, view_inp);
    dim3 grid((HWSZ + 255) / 256, 2);
    warp_kernel<<<grid, 256>>>(R0, t0, R1, t1, radii, out);
}

// round 13
// speedup vs baseline: 1.3413x; 1.0613x over previous
#include <cuda_runtime.h>

#define HH 512
#define WW 1024
#define DD 32
#define HWSZ (HH*WW)

// Packed RGBA (A unused) copies of the two source views. 16 MB static scratch.
__device__ float4 g_img[2][HWSZ];

__global__ void pack_kernel(const float* __restrict__ ref, const float* __restrict__ inp) {
    int i = blockIdx.x * blockDim.x + threadIdx.x;   // quad index
    if (i >= HWSZ / 4) return;
    const float4* r4 = (const float4*)ref;
    const float4* i4 = (const float4*)inp;
    float4 a0 = r4[i], a1 = r4[i + HWSZ/4], a2 = r4[i + 2*(HWSZ/4)];
    float4 b0 = i4[i], b1 = i4[i + HWSZ/4], b2 = i4[i + 2*(HWSZ/4)];
    int o = i << 2;
    g_img[0][o+0] = make_float4(a0.x, a1.x, a2.x, 0.f);
    g_img[0][o+1] = make_float4(a0.y, a1.y, a2.y, 0.f);
    g_img[0][o+2] = make_float4(a0.z, a1.z, a2.z, 0.f);
    g_img[0][o+3] = make_float4(a0.w, a1.w, a2.w, 0.f);
    g_img[1][o+0] = make_float4(b0.x, b1.x, b2.x, 0.f);
    g_img[1][o+1] = make_float4(b0.y, b1.y, b2.y, 0.f);
    g_img[1][o+2] = make_float4(b0.z, b1.z, b2.z, 0.f);
    g_img[1][o+3] = make_float4(b0.w, b1.w, b2.w, 0.f);
}

// Exact f32 constants as the reference's fp32 trace sees them.
#define ANGC    0.006135923151542565f   // f32(2*pi/1024) == f32(pi/512)
#define SCALEF  162.97466172610083f     // f32(W/(2*pi)) == f32(H/pi) = 512/pi
#define SCALE2F 325.94932345220166f     // 2*SCALEF
#define PIF     3.141592653589793f
#define MAGICF  12582912.0f             // 2^23 + 2^22: float->int round trick

__device__ __forceinline__ float frcp_ap(float x) {
    float r; asm("rcp.approx.f32 %0, %1;" : "=f"(r) : "f"(x)); return r;
}
__device__ __forceinline__ float fsqrt_ap(float x) {
    float r; asm("sqrt.approx.f32 %0, %1;" : "=f"(r) : "f"(x)); return r;
}

// S * atan(t) for t in [0,1]: SLEEF 8-coef minimax (~1 ulp), grid scale folded.
__device__ __forceinline__ float atan_core_s(float t, float S) {
    float t2 = t * t;
    float u = 0.00282363896258175373f;
    u = fmaf(u, t2, -0.0159569028764963150f);
    u = fmaf(u, t2,  0.0425049886107444763f);
    u = fmaf(u, t2, -0.0748900920152664184f);
    u = fmaf(u, t2,  0.106347933411598205f);
    u = fmaf(u, t2, -0.142027363181114196f);
    u = fmaf(u, t2,  0.199926957488059997f);
    u = fmaf(u, t2, -0.333331018686294555f);
    float st = S * t;
    return fmaf(t2 * u, st, st);
}

// SCALEF * mod(atan2(y,x), 2pi): quadrant constants exact (256/512/1024).
__device__ __forceinline__ float atan2_2pi_s(float y, float x) {
    float ax = fabsf(x), ay = fabsf(y);
    float mx = fmaxf(ax, ay), mn = fminf(ax, ay);
    float a = atan_core_s(mn * frcp_ap(mx), SCALEF);
    if (ay > ax)  a = 256.0f - a;
    if (x < 0.f)  a = 512.0f - a;
    if (y < 0.f)  a = 1024.0f - a;
    return a;
}

// SCALEF * atan2(rho, z) for rho >= 0 (polar angle in [0, 512]).
__device__ __forceinline__ float atan2_phi_s(float rho, float z) {
    float az = fabsf(z);
    float mx = fmaxf(az, rho), mn = fminf(az, rho);
    float a = atan_core_s(mn * frcp_ap(mx), SCALEF);
    if (rho > az) a = 256.0f - a;
    if (z < 0.f)  a = 512.0f - a;
    return a;
}

// SCALE2F * atan2(y,x) for y,x >= 0 (pole-path half-angle acos).
__device__ __forceinline__ float atan2_pos_s(float y, float x) {
    float mx = fmaxf(x, y), mn = fminf(x, y);
    float a = atan_core_s(mn * frcp_ap(mx), SCALE2F);
    return (y > x) ? (512.0f - a) : a;
}

__device__ __forceinline__ float3 bisample(const float4* __restrict__ im, float gx, float gy) {
    // Magic-number floor: mantissa low 23 bits = 0x400000 + floor(g), exact.
    float fx = (gx - 0.5f) + MAGICF;
    float fy = (gy - 0.5f) + MAGICF;
    float wx = gx - (fx - MAGICF);
    float wy = gy - (fy - MAGICF);
    int bx = __float_as_int(fx);
    int x0 = bx & (WW - 1);                // 0x400000 is a multiple of 1024
    int x1 = (bx + 1) & (WW - 1);
    int iy = (__float_as_int(fy) & 0x7FFFFF) - 0x400000;   // in [-1, 511]
    int y0 = max(iy, 0);
    int y1 = min(y0 + 1, HH - 1);
    const float4* r0p = im + (y0 << 10);
    const float4* r1p = im + (y1 << 10);
    float4 a = __ldg(r0p + x0);
    float4 b = __ldg(r0p + x1);
    float4 c = __ldg(r1p + x0);
    float4 d = __ldg(r1p + x1);
    float u = 1.0f - wx, vv = 1.0f - wy;
    float w00 = u * vv, w01 = wx * vv, w10 = u * wy, w11 = wx * wy;
    float3 o;
    o.x = fmaf(w00, a.x, fmaf(w01, b.x, fmaf(w10, c.x, w11 * d.x)));
    o.y = fmaf(w00, a.y, fmaf(w01, b.y, fmaf(w10, c.y, w11 * d.y)));
    o.z = fmaf(w00, a.z, fmaf(w10, c.z, fmaf(w01, b.z, w11 * d.z)));
    return o;
}

// One block = one (pixel-tile, view); blockIdx.y selects the view.
__global__ void __launch_bounds__(256, 5)
warp_kernel(const float* __restrict__ R0, const float* __restrict__ t0,
            const float* __restrict__ R1, const float* __restrict__ t1,
            const float* __restrict__ radii, float* __restrict__ out) {
    __shared__ float s_r[DD];
    int tid = threadIdx.x;
    if (tid < DD) s_r[tid] = __ldg(radii + tid);
    __syncthreads();

    int v = blockIdx.y;
    int idx = blockIdx.x * blockDim.x + tid;
    int h = idx >> 10;
    int w = idx & (WW - 1);

    // Pixel-center angles, bit-matching the reference.
    float theta = __fmul_rn((float)w + 0.5f, ANGC);
    float phi   = __fmul_rn((float)h + 0.5f, ANGC);
    float st = sinf(theta), ct = cosf(theta);
    float sp = sinf(phi),   cp = cosf(phi);
    float dx = __fmul_rn(sp, ct);
    float dy = __fmul_rn(sp, st);
    float dz = cp;

    const float* R = v ? R1 : R0;
    const float* t = v ? t1 : t0;
    float r00 = __ldg(R + 0), r01 = __ldg(R + 1), r02 = __ldg(R + 2);
    float r10 = __ldg(R + 3), r11 = __ldg(R + 4), r12 = __ldg(R + 5);
    float r20 = __ldg(R + 6), r21 = __ldg(R + 7), r22 = __ldg(R + 8);
    float tx = __ldg(t + 0),  ty = __ldg(t + 1),  tz = __ldg(t + 2);

    // Hoisted rotated ray q = R*d: p(r) = r*q + t. Rounding here deviates
    // ~2 ulp from the reference's per-depth replica chain — harmless except
    // near poles, where the gated slow path recomputes the exact replica.
    float qx = fmaf(r00, dx, fmaf(r01, dy, r02 * dz));
    float qy = fmaf(r10, dx, fmaf(r11, dy, r12 * dz));
    float qz = fmaf(r20, dx, fmaf(r21, dy, r22 * dz));

    const float4* im = g_img[v];
    float* ob = out + (size_t)(v * 3) * HWSZ + idx;

#pragma unroll 2
    for (int d = 0; d < DD; d++) {
        float r = s_r[d];
        float px = fmaf(r, qx, tx);
        float py = fmaf(r, qy, ty);
        float pz = fmaf(r, qz, tz);
        float sxy = fmaf(px, px, py * py);

        float gx, gy;
        // Pole gate: sin^2(phi_sampled) < 1/16  <=>  15*sxy < pz^2.
        // Warp-coherent (lanes share h). 97% take the cheap path.
        if (15.0f * sxy < pz * pz) {
            // ---- bit-exact replica of the reference fp32 chain. R10 proved
            // this is load-bearing where 1/sin(phi) amplification is large:
            // per-depth rotation rounding, div.rn+sqrt.rn nz, half-angle acos.
            float rx = __fmul_rn(r, dx);
            float ry = __fmul_rn(r, dy);
            float rz = __fmul_rn(r, dz);
            float pxr = __fadd_rn(fmaf(r02, rz, fmaf(r01, ry, __fmul_rn(r00, rx))), tx);
            float pyr = __fadd_rn(fmaf(r12, rz, fmaf(r11, ry, __fmul_rn(r10, rx))), ty);
            float pzr = __fadd_rn(fmaf(r22, rz, fmaf(r21, ry, __fmul_rn(r20, rx))), tz);
            float s = __fadd_rn(__fadd_rn(__fmul_rn(pxr, pxr), __fmul_rn(pyr, pyr)),
                                __fmul_rn(pzr, pzr));
            float nz = __fdiv_rn(pzr, __fsqrt_rn(s));
            nz = fminf(fmaxf(nz, -1.0f), 1.0f);
            float xx = __fmul_rn(nz, nz);
            float yy = fsqrt_ap(__fadd_rn(1.0f, -xx));
            float xpn = __fadd_rn(1.0f, nz);
            float ha_s = atan2_pos_s(yy, xpn);
            gy = (nz != -1.0f) ? (ha_s - 0.5f) : fmaf(PIF, SCALEF, -0.5f);
            gx = atan2_2pi_s(pyr, pxr) - 0.5f;
        } else {
            // Cheap path: phi = atan2(rho, pz) == acos(nz) — no normalize,
            // no clamp, no yy. All deviations unamplified away from poles.
            float rho = fsqrt_ap(sxy);
            gy = atan2_phi_s(rho, pz) - 0.5f;
            gx = atan2_2pi_s(py, px) - 0.5f;
        }

        float3 smp = bisample(im, gx, gy);
        ob[0 * HWSZ] = smp.x;
        ob[1 * HWSZ] = smp.y;
        ob[2 * HWSZ] = smp.z;
        ob += 6 * HWSZ;
    }
}

extern "C" void kernel_launch(void* const* d_in, const int* in_sizes, int n_in,
                              void* d_out, int out_size) {
    const float* view_ref = (const float*)d_in[0];
    const float* view_inp = (const float*)d_in[1];
    const float* R0 = (const float*)d_in[2];
    const float* t0 = (const float*)d_in[3];
    const float* R1 = (const float*)d_in[4];
    const float* t1 = (const float*)d_in[5];
    const float* radii = (const float*)d_in[6];
    float* out = (float*)d_out;

    pack_kernel<<<(HWSZ / 4 + 255) / 256, 256>>>(view_ref, view_inp);
    dim3 grid((HWSZ + 255) / 256, 2);
    warp_kernel<<<grid, 256>>>(R0, t0, R1, t1, radii, out);
}